// round 7
// baseline (speedup 1.0000x reference)
#include <cuda_runtime.h>
#include <cstdint>

#define N_GAUSS 4096
#define NSLICE  4
#define EPSF    1e-6f
// -0.5 * log2(e)
#define NHL2E  -0.72134752044448170367996234050095f
// pixel x stride for W=8 (16 columns apart)
#define HSTEP   (16.0f * (2.0f / 127.0f))
#define MAGICF  12582912.0f   // 1.5 * 2^23

// per-(slice, subchunk, pixel) partial sums (S1, S2); 16 subchunks of 256
__device__ float2 g_partial[NSLICE * 16 * 16384];

// ---------------------------------------------------------------------------
// packed f32x2 helpers
// ---------------------------------------------------------------------------
__device__ __forceinline__ uint64_t pk2(float lo, float hi) {
    uint64_t r;
    asm("mov.b64 %0, {%1,%2};" : "=l"(r) : "f"(lo), "f"(hi));
    return r;
}
__device__ __forceinline__ void upk2(uint64_t v, float& lo, float& hi) {
    asm("mov.b64 {%0,%1}, %2;" : "=f"(lo), "=f"(hi) : "l"(v));
}
__device__ __forceinline__ uint64_t fma2(uint64_t a, uint64_t b, uint64_t c) {
    uint64_t d;
    asm("fma.rn.f32x2 %0, %1, %2, %3;" : "=l"(d) : "l"(a), "l"(b), "l"(c));
    return d;
}
__device__ __forceinline__ uint64_t mul2(uint64_t a, uint64_t b) {
    uint64_t d;
    asm("mul.rn.f32x2 %0, %1, %2;" : "=l"(d) : "l"(a), "l"(b));
    return d;
}
__device__ __forceinline__ uint64_t add2(uint64_t a, uint64_t b) {
    uint64_t d;
    asm("add.rn.f32x2 %0, %1, %2;" : "=l"(d) : "l"(a), "l"(b));
    return d;
}
__device__ __forceinline__ float ex2a(float x) {
    float r;
    asm("ex2.approx.f32 %0, %1;" : "=f"(r) : "f"(x));
    return r;
}

// ---------------------------------------------------------------------------
// Fused render kernel.
// Block = one (slice, subchunk of 256 gaussians, 8-row tile). 128 threads.
// Phase A: block computes its 256 gaussians' coefficients into smem
//          (pair-interleaved, 128 pairs x 64B).
// Phase B: thread = 8 pixels in one row (cols j + 16p), incremental dx,
//          2 gaussians/iter packed f32x2. Pixel 7 uses poly-exp2 (fma+alu
//          pipes) instead of MUFU ex2 to balance pipes.
// grid = 1024 = 4 slices * 16 subchunks * 16 tiles.
// ---------------------------------------------------------------------------
__global__ void __launch_bounds__(128, 7) k_render_part(
        const float* __restrict__ means,
        const float* __restrict__ scales,
        const float* __restrict__ rot,
        const float* __restrict__ opac,
        const float* __restrict__ feat) {
    __shared__ __align__(16) float smt[128 * 16];   // 8KB
    __shared__ float red[4];

    int bid  = blockIdx.x;
    int s    = bid >> 8;         // slice
    int sub  = (bid >> 4) & 15;  // subchunk (256 gaussians = 128 pairs)
    int tile = bid & 15;         // 8-row tile
    int tid  = threadIdx.x;

    // ---- Phase A0: block-local max over all 4096 z-scales ----
    {
        float m = 0.0f;
        for (int k = tid; k < N_GAUSS; k += 128)
            m = fmaxf(m, __ldg(&scales[k * 3 + 2]));
#pragma unroll
        for (int o = 16; o > 0; o >>= 1)
            m = fmaxf(m, __shfl_xor_sync(0xffffffffu, m, o));
        if ((tid & 31) == 0) red[tid >> 5] = m;
    }
    __syncthreads();
    float md = 3.0f * fmaxf(fmaxf(red[0], red[1]), fmaxf(red[2], red[3]));

    // ---- Phase A1: coefficients for this thread's gaussian pair ----
    {
        float zs = -0.15f + 0.1f * (float)s;
        float* tp = smt + tid * 16;
#pragma unroll
        for (int h = 0; h < 2; h++) {
            int k = sub * 256 + 2 * tid + h;

            float qw = rot[k * 4 + 0], qx = rot[k * 4 + 1];
            float qy = rot[k * 4 + 2], qz = rot[k * 4 + 3];
            float inq = rsqrtf(qw * qw + qx * qx + qy * qy + qz * qz);
            float w = qw * inq, x = qx * inq, y = qy * inq, z = qz * inq;

            float r00 = 1.f - 2.f * (y * y + z * z);
            float r01 = 2.f * (x * y - w * z);
            float r02 = 2.f * (x * z + w * y);
            float r10 = 2.f * (x * y + w * z);
            float r11 = 1.f - 2.f * (x * x + z * z);
            float r12 = 2.f * (y * z - w * x);
            float r20 = 2.f * (x * z - w * y);
            float r21 = 2.f * (y * z + w * x);
            float r22 = 1.f - 2.f * (x * x + y * y);

            float sx = scales[k * 3 + 0], sy = scales[k * 3 + 1], sz = scales[k * 3 + 2];
            float m00 = r00 * sx, m01 = r01 * sy, m02 = r02 * sz;
            float m10 = r10 * sx, m11 = r11 * sy, m12 = r12 * sz;
            float m20 = r20 * sx, m21 = r21 * sy, m22 = r22 * sz;

            float c00 = m00 * m00 + m01 * m01 + m02 * m02;
            float c01 = m00 * m10 + m01 * m11 + m02 * m12;
            float c11 = m10 * m10 + m11 * m11 + m12 * m12;
            float c02 = m00 * m20 + m01 * m21 + m02 * m22;
            float c12 = m10 * m20 + m11 * m21 + m12 * m22;
            float c22 = m20 * m20 + m21 * m21 + m22 * m22;

            float szz = c22 + EPSF;
            float rx = c02 / szz;
            float ry = c12 / szz;

            float s00 = c00 - c02 * c02 / szz + EPSF;
            float s01 = c01 - c02 * c12 / szz;
            float s11 = c11 - c12 * c12 / szz + EPSF;
            float det = s00 * s11 - s01 * s01;
            float A  = s11 / det;
            float Bc = -s01 / det;
            float D  = s00 / det;

            float mz = means[k * 3 + 2];
            float zoff = zs - mz;
            float mx = means[k * 3 + 0] + rx * zoff;
            float my = means[k * 3 + 1] + ry * zoff;
            float mask = (fabsf(mz - zs) < md) ? 1.0f : 0.0f;
            float op = opac[k];
            float ft = feat[k];

            tp[0  + h] = NHL2E * A;
            tp[2  + h] = NHL2E * 2.0f * Bc;
            tp[4  + h] = NHL2E * D;
            tp[6  + h] = -mx;
            tp[8  + h] = -my;
            tp[10 + h] = mask * op;
            tp[12 + h] = mask * op * ft;
            tp[14 + h] = 0.0f;
        }
    }
    __syncthreads();

    // ---- Phase B: main loop ----
    int i = tile * 8 + (tid >> 4);   // row
    int j = tid & 15;                // base col; pixels j + 16p

    float yv = -1.0f + (float)i * (2.0f / 127.0f);
    float x0 = -1.0f + (float)j * (2.0f / 127.0f);

    uint64_t Y  = pk2(yv, yv);
    uint64_t X0 = pk2(x0, x0);
    uint64_t Hc = pk2(HSTEP, HSTEP);

    // poly-exp2 constants (packed)
    uint64_t MG   = pk2(MAGICF, MAGICF);
    uint64_t nMG  = pk2(-MAGICF, -MAGICF);
    uint64_t NEG1 = pk2(-1.0f, -1.0f);
    uint64_t C4 = pk2(0.00961812911f, 0.00961812911f);
    uint64_t C3 = pk2(0.0555041087f, 0.0555041087f);
    uint64_t C2 = pk2(0.240226507f, 0.240226507f);
    uint64_t C1 = pk2(0.693147182f, 0.693147182f);
    uint64_t ONEp = pk2(1.0f, 1.0f);

    uint64_t S1[8], S2[8];
#pragma unroll
    for (int p = 0; p < 8; p++) { S1[p] = pk2(0.f, 0.f); S2[p] = pk2(0.f, 0.f); }

    const ulonglong2* sp = reinterpret_cast<const ulonglong2*>(smt);
    const unsigned long long* sp64 = reinterpret_cast<const unsigned long long*>(smt);

#pragma unroll 2
    for (int kp = 0; kp < 128; kp++) {
        ulonglong2 v0 = sp[kp * 4 + 0];   // NA | NB2
        ulonglong2 v1 = sp[kp * 4 + 1];   // ND | NMX
        ulonglong2 v2 = sp[kp * 4 + 2];   // NMY | OP
        uint64_t  OFT = sp64[kp * 8 + 6]; // OFT

        uint64_t dy = add2(Y, v2.x);
        uint64_t t0 = mul2(v0.y, dy);            // 2B' * dy
        uint64_t t2 = mul2(mul2(v1.x, dy), dy);  // D' * dy^2

        uint64_t dx = add2(X0, v1.y);
#pragma unroll
        for (int p = 0; p < 8; p++) {
            uint64_t q = fma2(fma2(v0.x, dx, t0), dx, t2);  // -0.5*log2e*maha
            uint64_t g;
            if (p != 7) {
                float l, h;
                upk2(q, l, h);
                g = pk2(ex2a(l), ex2a(h));
            } else {
                // polynomial exp2 on fma+alu pipes (balances MUFU).
                // Range reduction (FIXED): n = (q+MAGIC) - MAGIC exactly,
                // then r = q - n exactly; r in [-0.5, 0.5].
                float ql, qh;
                upk2(q, ql, qh);
                ql = fmaxf(ql, -125.0f);
                qh = fmaxf(qh, -125.0f);
                uint64_t qc = pk2(ql, qh);
                uint64_t T  = add2(qc, MG);        // MAGIC + n (bits hold n)
                float tl, th;
                upk2(T, tl, th);
                uint64_t nf = add2(T, nMG);        // n as float (exact)
                uint64_t r  = fma2(nf, NEG1, qc);  // r = q - n (exact)
                uint64_t u = fma2(C4, r, C3);
                u = fma2(u, r, C2);
                u = fma2(u, r, C1);
                uint64_t pr = fma2(u, r, ONEp);    // exp2(r)
                float pl, ph;
                upk2(pr, pl, ph);
                // splice exponent: g = p * 2^n via integer add of (bits(T)<<23)
                float gl = __int_as_float((__float_as_int(tl) << 23) + __float_as_int(pl));
                float gh = __int_as_float((__float_as_int(th) << 23) + __float_as_int(ph));
                g = pk2(gl, gh);
            }
            S2[p] = fma2(g, v2.y, S2[p]);
            S1[p] = fma2(mul2(g, g), OFT, S1[p]);
            dx = add2(dx, Hc);
        }
    }

    int p0 = i * 128 + j;
    float2* dst = g_partial + (size_t)(s * 16 + sub) * 16384;
#pragma unroll
    for (int p = 0; p < 8; p++) {
        float s1l, s1h, s2l, s2h;
        upk2(S1[p], s1l, s1h);
        upk2(S2[p], s2l, s2h);
        dst[p0 + 16 * p] = make_float2(s1l + s1h, s2l + s2h);
    }
}

// ---------------------------------------------------------------------------
// Fold subchunks (4 per reference chunk), then transmittance recurrence
// over the 4 chunks (== reference scan).
// ---------------------------------------------------------------------------
__global__ void __launch_bounds__(256) k_fold(float* __restrict__ out) {
    int g = blockIdx.x * 256 + threadIdx.x;   // 65536
    int s = g >> 14;
    int p = g & 16383;
    const float2* base = g_partial + (size_t)s * 16 * 16384 + p;

    float img = 0.0f, T = 1.0f;
#pragma unroll
    for (int c = 0; c < 4; c++) {
        float S1 = 0.0f, S2 = 0.0f;
#pragma unroll
        for (int u = 0; u < 4; u++) {
            float2 v = base[(size_t)(c * 4 + u) * 16384];
            S1 += v.x;
            S2 += v.y;
        }
        img = fmaf(T, S1, img);    // img += (1-acc) * S1
        T   = T * (1.0f - S2);     // (1-acc) *= (1 - S2)
    }
    out[g] = img;   // BACKGROUND == 0
}

// ---------------------------------------------------------------------------
extern "C" void kernel_launch(void* const* d_in, const int* in_sizes, int n_in,
                              void* d_out, int out_size) {
    const float* means  = (const float*)d_in[0];
    const float* scales = (const float*)d_in[1];
    const float* rots   = (const float*)d_in[2];
    const float* opac   = (const float*)d_in[3];
    const float* feat   = (const float*)d_in[4];
    float* out = (float*)d_out;

    k_render_part<<<1024, 128>>>(means, scales, rots, opac, feat);
    k_fold<<<256, 256>>>(out);
}

// round 8
// speedup vs baseline: 1.0416x; 1.0416x over previous
#include <cuda_runtime.h>
#include <cstdint>

#define N_GAUSS 4096
#define NPAIR   2048
#define NSLICE  4
#define EPSF    1e-6f
// +0.5 * log2(e)
#define HL2E    0.72134752044448170367996234050095f
// pixel x stride for W=8 (16 columns apart)
#define HSTEP   (16.0f * (2.0f / 127.0f))

// pair-interleaved table: per slice, per pair kp, 16 floats:
// [SA(a,b), E(a,b), Cp(a,b), SM(a,b), VH(a,b), NMY(a,b), OP(a,b), OFT(a,b)]
// L = +0.5*log2e*maha = v^2 + Cp*dy^2,  v = SA*dx + E*dy = SA*x + SM + E*dy
// SM = -SA*mx, VH = SA*HSTEP, NMY = -my, OP = mask*op, OFT = mask*op*ft
__device__ __align__(16) float g_table[NSLICE * NPAIR * 16];
// per-(slice, subchunk, pixel) partial sums (S1, S2); 16 subchunks of 256
__device__ float2 g_partial[NSLICE * 16 * 16384];

// ---------------------------------------------------------------------------
// packed f32x2 helpers
// ---------------------------------------------------------------------------
__device__ __forceinline__ uint64_t pk2(float lo, float hi) {
    uint64_t r;
    asm("mov.b64 %0, {%1,%2};" : "=l"(r) : "f"(lo), "f"(hi));
    return r;
}
__device__ __forceinline__ void upk2(uint64_t v, float& lo, float& hi) {
    asm("mov.b64 {%0,%1}, %2;" : "=f"(lo), "=f"(hi) : "l"(v));
}
__device__ __forceinline__ uint64_t fma2(uint64_t a, uint64_t b, uint64_t c) {
    uint64_t d;
    asm("fma.rn.f32x2 %0, %1, %2, %3;" : "=l"(d) : "l"(a), "l"(b), "l"(c));
    return d;
}
__device__ __forceinline__ uint64_t mul2(uint64_t a, uint64_t b) {
    uint64_t d;
    asm("mul.rn.f32x2 %0, %1, %2;" : "=l"(d) : "l"(a), "l"(b));
    return d;
}
__device__ __forceinline__ uint64_t add2(uint64_t a, uint64_t b) {
    uint64_t d;
    asm("add.rn.f32x2 %0, %1, %2;" : "=l"(d) : "l"(a), "l"(b));
    return d;
}
__device__ __forceinline__ float ex2a(float x) {
    float r;
    asm("ex2.approx.f32 %0, %1;" : "=f"(r) : "f"(x));
    return r;
}
// scalar poly exp2 for q in [-inf, 0] (fma/alu pipes; constants -> URs).
// Range reduction verified correct in round 7.
__device__ __forceinline__ float poly_exp2(float q) {
    q = fmaxf(q, -125.0f);
    float T = q + 12582912.0f;          // MAGIC = 1.5*2^23
    float n = T - 12582912.0f;          // exact integer part
    float r = q - n;                    // exact, in [-0.5, 0.5]
    float u = fmaf(0.00961812911f, r, 0.0555041087f);
    u = fmaf(u, r, 0.240226507f);
    u = fmaf(u, r, 0.693147182f);
    float p = fmaf(u, r, 1.0f);
    return __int_as_float((__float_as_int(T) << 23) + __float_as_int(p));
}

// ---------------------------------------------------------------------------
// Kernel 1: precompute. One thread per (gaussian, slice): 16384 threads.
// Each block redundantly computes max(scales[:,2]).
// ---------------------------------------------------------------------------
__global__ void __launch_bounds__(128) k_precompute(
        const float* __restrict__ means,
        const float* __restrict__ scales,
        const float* __restrict__ rot,
        const float* __restrict__ opac,
        const float* __restrict__ feat) {
    __shared__ float red[4];
    int lid = threadIdx.x & 31;
    int wid = threadIdx.x >> 5;

    float m = 0.0f;
    for (int k = threadIdx.x; k < N_GAUSS; k += 128)
        m = fmaxf(m, __ldg(&scales[k * 3 + 2]));
#pragma unroll
    for (int o = 16; o > 0; o >>= 1)
        m = fmaxf(m, __shfl_xor_sync(0xffffffffu, m, o));
    if (lid == 0) red[wid] = m;
    __syncthreads();
    float md = 3.0f * fmaxf(fmaxf(red[0], red[1]), fmaxf(red[2], red[3]));

    int g = blockIdx.x * 128 + threadIdx.x;   // 16384
    int k = g & (N_GAUSS - 1);
    int s = g >> 12;

    float4 q4 = __ldg(reinterpret_cast<const float4*>(rot) + k);
    float inq = rsqrtf(q4.x * q4.x + q4.y * q4.y + q4.z * q4.z + q4.w * q4.w);
    float w = q4.x * inq, x = q4.y * inq, y = q4.z * inq, z = q4.w * inq;

    float r00 = 1.f - 2.f * (y * y + z * z);
    float r01 = 2.f * (x * y - w * z);
    float r02 = 2.f * (x * z + w * y);
    float r10 = 2.f * (x * y + w * z);
    float r11 = 1.f - 2.f * (x * x + z * z);
    float r12 = 2.f * (y * z - w * x);
    float r20 = 2.f * (x * z - w * y);
    float r21 = 2.f * (y * z + w * x);
    float r22 = 1.f - 2.f * (x * x + y * y);

    float sx = scales[k * 3 + 0], sy = scales[k * 3 + 1], sz = scales[k * 3 + 2];
    float m00 = r00 * sx, m01 = r01 * sy, m02 = r02 * sz;
    float m10 = r10 * sx, m11 = r11 * sy, m12 = r12 * sz;
    float m20 = r20 * sx, m21 = r21 * sy, m22 = r22 * sz;

    float c00 = m00 * m00 + m01 * m01 + m02 * m02;
    float c01 = m00 * m10 + m01 * m11 + m02 * m12;
    float c11 = m10 * m10 + m11 * m11 + m12 * m12;
    float c02 = m00 * m20 + m01 * m21 + m02 * m22;
    float c12 = m10 * m20 + m11 * m21 + m12 * m22;
    float c22 = m20 * m20 + m21 * m21 + m22 * m22;

    float szz = c22 + EPSF;
    float rx = c02 / szz;
    float ry = c12 / szz;

    float s00 = c00 - c02 * c02 / szz + EPSF;
    float s01 = c01 - c02 * c12 / szz;
    float s11 = c11 - c12 * c12 / szz + EPSF;
    float det = s00 * s11 - s01 * s01;
    float A  = s11 / det;
    float Bc = -s01 / det;
    float D  = s00 / det;

    // positive-definite scaled form: L = a dx^2 + b dx dy + c dy^2
    float a = HL2E * A;
    float b = HL2E * 2.0f * Bc;
    float c = HL2E * D;
    float SA = sqrtf(a);
    float E  = b / (2.0f * SA);
    float Cp = c - E * E;               // = HL2E * det(inv2d)/A > 0
    if (Cp < 0.0f) Cp = 0.0f;           // guard fp rounding

    float mz = means[k * 3 + 2];
    float zs = -0.15f + 0.1f * (float)s;   // linspace(-0.15, 0.15, 4)
    float zoff = zs - mz;
    float mx = means[k * 3 + 0] + rx * zoff;
    float my = means[k * 3 + 1] + ry * zoff;
    float mask = (fabsf(mz - zs) < md) ? 1.0f : 0.0f;
    float op = opac[k];
    float ft = feat[k];

    int kp = k >> 1;
    int h  = k & 1;
    float* t = g_table + ((size_t)(s * NPAIR + kp) * 16);
    t[0  + h] = SA;
    t[2  + h] = E;
    t[4  + h] = Cp;
    t[6  + h] = -SA * mx;     // SM
    t[8  + h] = SA * HSTEP;   // VH
    t[10 + h] = -my;          // NMY
    t[12 + h] = mask * op;
    t[14 + h] = mask * op * ft;
}

// ---------------------------------------------------------------------------
// Kernel 2: partial render.
// Block = one (slice, subchunk of 256 gaussians, 8-row tile). 128 threads.
// Thread: 8 pixels in one row (cols j + 16p); v-chain increments by VH.
// Pixel 7 uses scalar poly-exp2 (fma/alu) instead of MUFU to balance pipes.
// grid = 1024 = 4 slices * 16 subchunks * 16 tiles.
// ---------------------------------------------------------------------------
__global__ void __launch_bounds__(128, 7) k_render_part() {
    __shared__ __align__(16) uint4 smt[512];   // 128 pairs * 64B = 8KB

    int bid  = blockIdx.x;
    int s    = bid >> 8;         // slice
    int sub  = (bid >> 4) & 15;  // subchunk (256 gaussians = 128 pairs)
    int tile = bid & 15;         // 8-row tile
    int tid  = threadIdx.x;

    const uint4* gsrc = reinterpret_cast<const uint4*>(g_table)
                        + ((size_t)s * NPAIR + (size_t)sub * 128) * 4;
#pragma unroll 4
    for (int t = tid; t < 512; t += 128)
        smt[t] = __ldg(gsrc + t);
    __syncthreads();

    int i = tile * 8 + (tid >> 4);   // row
    int j = tid & 15;                // base col; pixels j + 16p

    float yv = -1.0f + (float)i * (2.0f / 127.0f);
    float x0 = -1.0f + (float)j * (2.0f / 127.0f);

    uint64_t Y  = pk2(yv, yv);
    uint64_t X0 = pk2(x0, x0);

    uint64_t S1[8], S2[8];
#pragma unroll
    for (int p = 0; p < 8; p++) { S1[p] = pk2(0.f, 0.f); S2[p] = pk2(0.f, 0.f); }

    const ulonglong2* sp = reinterpret_cast<const ulonglong2*>(smt);

#pragma unroll 2
    for (int kp = 0; kp < 128; kp++) {
        ulonglong2 u0 = sp[kp * 4 + 0];   // SA | E
        ulonglong2 u1 = sp[kp * 4 + 1];   // Cp | SM
        ulonglong2 u2 = sp[kp * 4 + 2];   // VH | NMY
        ulonglong2 u3 = sp[kp * 4 + 3];   // OP | OFT

        uint64_t dy = add2(Y, u2.y);
        uint64_t w  = mul2(mul2(u1.x, dy), dy);  // Cp*dy^2
        uint64_t v  = fma2(u0.x, X0, u1.y);      // SA*x0 + SM
        v = fma2(u0.y, dy, v);                   // + E*dy

#pragma unroll
        for (int p = 0; p < 8; p++) {
            uint64_t t = fma2(v, v, w);          // L = +0.721*maha (>= 0)
            float tl, th;
            upk2(t, tl, th);
            uint64_t g;
            if (p != 7) {
                g = pk2(ex2a(-tl), ex2a(-th));
            } else {
                g = pk2(poly_exp2(-tl), poly_exp2(-th));
            }
            S2[p] = fma2(g, u3.x, S2[p]);
            S1[p] = fma2(mul2(g, g), u3.y, S1[p]);
            v = add2(v, u2.x);                   // v += SA*HSTEP
        }
    }

    int p0 = i * 128 + j;
    float2* dst = g_partial + (size_t)(s * 16 + sub) * 16384;
#pragma unroll
    for (int p = 0; p < 8; p++) {
        float s1l, s1h, s2l, s2h;
        upk2(S1[p], s1l, s1h);
        upk2(S2[p], s2l, s2h);
        dst[p0 + 16 * p] = make_float2(s1l + s1h, s2l + s2h);
    }
}

// ---------------------------------------------------------------------------
// Kernel 3: fold subchunks (4 per reference chunk), then transmittance
// recurrence over the 4 chunks (== reference scan).
// ---------------------------------------------------------------------------
__global__ void __launch_bounds__(256) k_fold(float* __restrict__ out) {
    int g = blockIdx.x * 256 + threadIdx.x;   // 65536
    int s = g >> 14;
    int p = g & 16383;
    const float2* base = g_partial + (size_t)s * 16 * 16384 + p;

    float img = 0.0f, T = 1.0f;
#pragma unroll
    for (int c = 0; c < 4; c++) {
        float S1 = 0.0f, S2 = 0.0f;
#pragma unroll
        for (int u = 0; u < 4; u++) {
            float2 v = base[(size_t)(c * 4 + u) * 16384];
            S1 += v.x;
            S2 += v.y;
        }
        img = fmaf(T, S1, img);    // img += (1-acc) * S1
        T   = T * (1.0f - S2);     // (1-acc) *= (1 - S2)
    }
    out[g] = img;   // BACKGROUND == 0
}

// ---------------------------------------------------------------------------
extern "C" void kernel_launch(void* const* d_in, const int* in_sizes, int n_in,
                              void* d_out, int out_size) {
    const float* means  = (const float*)d_in[0];
    const float* scales = (const float*)d_in[1];
    const float* rots   = (const float*)d_in[2];
    const float* opac   = (const float*)d_in[3];
    const float* feat   = (const float*)d_in[4];
    float* out = (float*)d_out;

    k_precompute<<<128, 128>>>(means, scales, rots, opac, feat);
    k_render_part<<<1024, 128>>>();
    k_fold<<<256, 256>>>(out);
}

// round 9
// speedup vs baseline: 1.3879x; 1.3325x over previous
#include <cuda_runtime.h>
#include <cstdint>

#define N_GAUSS 4096
#define NSLICE  4
#define EPSF    1e-6f
// +0.5 * log2(e)
#define HL2E    0.72134752044448170367996234050095f
// contiguous pixel x step
#define HPIX    (2.0f / 127.0f)
#define SA_THIN 40.0f

// table: per (slice, subchunk) of 128 pairs, 32 floats per pair (128B line):
// entry e for halves (a,b) at [2e],[2e+1]:
// e0 SA, e1 E, e2 SM(-SA*mx), e3 NCp(-Cp), e4 NMY(-my), e5 OP, e6 OFT,
// e7 DC(-2*Delta), e8 DD(-Delta^2), e9 R(2^-2Delta^2), e10..15 pad
__device__ __align__(16) float g_table[NSLICE * 16 * 128 * 32];
__device__ int g_nsafe_pairs[NSLICE * 16];
// per-(slice, subchunk, pixel) partial sums (S1, S2)
__device__ float2 g_partial[NSLICE * 16 * 16384];

// ---------------------------------------------------------------------------
__device__ __forceinline__ uint64_t pk2(float lo, float hi) {
    uint64_t r;
    asm("mov.b64 %0, {%1,%2};" : "=l"(r) : "f"(lo), "f"(hi));
    return r;
}
__device__ __forceinline__ void upk2(uint64_t v, float& lo, float& hi) {
    asm("mov.b64 {%0,%1}, %2;" : "=f"(lo), "=f"(hi) : "l"(v));
}
__device__ __forceinline__ uint64_t fma2(uint64_t a, uint64_t b, uint64_t c) {
    uint64_t d;
    asm("fma.rn.f32x2 %0, %1, %2, %3;" : "=l"(d) : "l"(a), "l"(b), "l"(c));
    return d;
}
__device__ __forceinline__ uint64_t mul2(uint64_t a, uint64_t b) {
    uint64_t d;
    asm("mul.rn.f32x2 %0, %1, %2;" : "=l"(d) : "l"(a), "l"(b));
    return d;
}
__device__ __forceinline__ uint64_t add2(uint64_t a, uint64_t b) {
    uint64_t d;
    asm("add.rn.f32x2 %0, %1, %2;" : "=l"(d) : "l"(a), "l"(b));
    return d;
}
__device__ __forceinline__ float ex2a(float x) {
    float r;
    asm("ex2.approx.f32 %0, %1;" : "=f"(r) : "f"(x));
    return r;
}

// ---------------------------------------------------------------------------
// Kernel 1: precompute + per-subchunk safe/thin partition.
// 64 blocks (slice, subchunk) x 256 threads (1 gaussian each).
// ---------------------------------------------------------------------------
__global__ void __launch_bounds__(256) k_precompute(
        const float* __restrict__ means,
        const float* __restrict__ scales,
        const float* __restrict__ rot,
        const float* __restrict__ opac,
        const float* __restrict__ feat) {
    __shared__ float red[8];
    __shared__ int wsum[8];

    int s   = blockIdx.x >> 4;
    int sub = blockIdx.x & 15;
    int t   = threadIdx.x;
    int lane = t & 31;
    int wid  = t >> 5;

    // block-local max over all 4096 z-scales
    {
        float m = 0.0f;
        for (int k = t; k < N_GAUSS; k += 256)
            m = fmaxf(m, __ldg(&scales[k * 3 + 2]));
#pragma unroll
        for (int o = 16; o > 0; o >>= 1)
            m = fmaxf(m, __shfl_xor_sync(0xffffffffu, m, o));
        if (lane == 0) red[wid] = m;
    }
    __syncthreads();
    float md = red[0];
#pragma unroll
    for (int u = 1; u < 8; u++) md = fmaxf(md, red[u]);
    md *= 3.0f;

    int k = sub * 256 + t;

    float4 q4 = __ldg(reinterpret_cast<const float4*>(rot) + k);
    float inq = rsqrtf(q4.x * q4.x + q4.y * q4.y + q4.z * q4.z + q4.w * q4.w);
    float w = q4.x * inq, x = q4.y * inq, y = q4.z * inq, z = q4.w * inq;

    float r00 = 1.f - 2.f * (y * y + z * z);
    float r01 = 2.f * (x * y - w * z);
    float r02 = 2.f * (x * z + w * y);
    float r10 = 2.f * (x * y + w * z);
    float r11 = 1.f - 2.f * (x * x + z * z);
    float r12 = 2.f * (y * z - w * x);
    float r20 = 2.f * (x * z - w * y);
    float r21 = 2.f * (y * z + w * x);
    float r22 = 1.f - 2.f * (x * x + y * y);

    float sx = scales[k * 3 + 0], sy = scales[k * 3 + 1], sz = scales[k * 3 + 2];
    float m00 = r00 * sx, m01 = r01 * sy, m02 = r02 * sz;
    float m10 = r10 * sx, m11 = r11 * sy, m12 = r12 * sz;
    float m20 = r20 * sx, m21 = r21 * sy, m22 = r22 * sz;

    float c00 = m00 * m00 + m01 * m01 + m02 * m02;
    float c01 = m00 * m10 + m01 * m11 + m02 * m12;
    float c11 = m10 * m10 + m11 * m11 + m12 * m12;
    float c02 = m00 * m20 + m01 * m21 + m02 * m22;
    float c12 = m10 * m20 + m11 * m21 + m12 * m22;
    float c22 = m20 * m20 + m21 * m21 + m22 * m22;

    float szz = c22 + EPSF;
    float rx = c02 / szz;
    float ry = c12 / szz;

    float s00 = c00 - c02 * c02 / szz + EPSF;
    float s01 = c01 - c02 * c12 / szz;
    float s11 = c11 - c12 * c12 / szz + EPSF;
    float det = s00 * s11 - s01 * s01;
    float A  = s11 / det;
    float Bc = -s01 / det;
    float D  = s00 / det;

    float a = HL2E * A;
    float b = HL2E * 2.0f * Bc;
    float c = HL2E * D;
    float SA = sqrtf(a);
    float E  = b / (2.0f * SA);
    float Cp = c - E * E;
    if (Cp < 0.0f) Cp = 0.0f;

    float Delta = SA * HPIX;
    float DC = -2.0f * Delta;
    float DD = -Delta * Delta;
    float R  = ex2a(2.0f * DD);

    // safe iff SA <= SA_THIN and finite (NaN -> exact path)
    int safe = (SA <= SA_THIN) ? 1 : 0;

    // block-wide partition: safe gaussians first (stable within warp order)
    unsigned bal = __ballot_sync(0xffffffffu, safe);
    unsigned ltmask = (1u << lane) - 1u;
    int w_safe_pre = __popc(bal & ltmask);
    int w_safe_tot = __popc(bal);
    if (lane == 0) wsum[wid] = w_safe_tot;
    __syncthreads();
    int safe_off = 0, n_safe = 0;
#pragma unroll
    for (int u = 0; u < 8; u++) {
        int v2 = wsum[u];
        if (u < wid) safe_off += v2;
        n_safe += v2;
    }
    int thin_off = n_safe + (32 * wid - safe_off);  // thin gaussians before my warp
    int pos = safe ? (safe_off + w_safe_pre)
                   : (thin_off + (lane - w_safe_pre));

    if (t == 0) g_nsafe_pairs[s * 16 + sub] = n_safe >> 1;

    // slice-dependent values
    float mz = means[k * 3 + 2];
    float zs = -0.15f + 0.1f * (float)s;
    float zoff = zs - mz;
    float mx = means[k * 3 + 0] + rx * zoff;
    float my = means[k * 3 + 1] + ry * zoff;
    float mask = (fabsf(mz - zs) < md) ? 1.0f : 0.0f;
    float op = opac[k];
    float ft = feat[k];

    int kp = pos >> 1;
    int h  = pos & 1;
    float* tp = g_table + ((size_t)((s * 16 + sub) * 128 + kp) * 32);
    tp[0  + h] = SA;
    tp[2  + h] = E;
    tp[4  + h] = -SA * mx;    // SM
    tp[6  + h] = -Cp;         // NCp
    tp[8  + h] = -my;         // NMY
    tp[10 + h] = mask * op;   // OP
    tp[12 + h] = mask * op * ft; // OFT
    tp[14 + h] = DC;
    tp[16 + h] = DD;
    tp[18 + h] = R;
    tp[20 + h] = 0.0f; tp[22 + h] = 0.0f; tp[24 + h] = 0.0f;
    tp[26 + h] = 0.0f; tp[28 + h] = 0.0f; tp[30 + h] = 0.0f;
}

// ---------------------------------------------------------------------------
// Kernel 2: partial render with exp recurrence along 8 contiguous pixels.
// Block = one (slice, subchunk of 256 gaussians, 8-row tile). 128 threads.
// Thread: 8 contiguous pixels in one row (cols 8*(tid&15) .. +7).
// grid = 1024 = 4 slices * 16 subchunks * 16 tiles.
// ---------------------------------------------------------------------------
__global__ void __launch_bounds__(128, 7) k_render_part() {
    __shared__ __align__(16) uint4 smt[1024];   // 128 pairs * 128B = 16KB

    int bid  = blockIdx.x;
    int s    = bid >> 8;
    int sub  = (bid >> 4) & 15;
    int tile = bid & 15;
    int tid  = threadIdx.x;

    const uint4* gsrc = reinterpret_cast<const uint4*>(g_table)
                        + (size_t)(s * 16 + sub) * 128 * 8;
#pragma unroll 8
    for (int t = tid; t < 1024; t += 128)
        smt[t] = __ldg(gsrc + t);
    int nsp = __ldg(&g_nsafe_pairs[s * 16 + sub]);
    __syncthreads();

    int i  = tile * 8 + (tid >> 4);      // row
    int jb = (tid & 15) * 8;             // first col of this thread's 8

    float yv = -1.0f + (float)i * (2.0f / 127.0f);
    float x0 = -1.0f + (float)jb * HPIX;

    uint64_t Y  = pk2(yv, yv);
    uint64_t X0 = pk2(x0, x0);
    const uint64_t SGN = 0x8000000080000000ULL;

    uint64_t S1[8], S2[8];
#pragma unroll
    for (int p = 0; p < 8; p++) { S1[p] = pk2(0.f, 0.f); S2[p] = pk2(0.f, 0.f); }

    const ulonglong2* sp = reinterpret_cast<const ulonglong2*>(smt);

    int kp = 0;
    // ---- safe pairs: 2 exps per pair, multiplicative chain across pixels ----
#pragma unroll 2
    for (; kp < nsp; kp++) {
        ulonglong2 u0 = sp[kp * 8 + 0];   // SA | E
        ulonglong2 u1 = sp[kp * 8 + 1];   // SM | NCp
        ulonglong2 u2 = sp[kp * 8 + 2];   // NMY | OP
        ulonglong2 u3 = sp[kp * 8 + 3];   // OFT | DC
        ulonglong2 u4 = sp[kp * 8 + 4];   // DD | R

        uint64_t dy = add2(Y, u2.x);
        uint64_t wv = mul2(mul2(u1.y, dy), dy);   // w' = -Cp*dy^2 <= 0
        uint64_t v  = fma2(u0.x, X0, u1.x);       // SA*x0 + SM
        v = fma2(u0.y, dy, v);                    // + E*dy
        uint64_t nv = v ^ SGN;                    // -v (alu)
        uint64_t q0 = fma2(v, nv, wv);            // -(v^2) + w' = -L0
        uint64_t qd = fma2(u3.y, v, u4.x);        // DC*v0 + DD

        float a2, b2, c2, d2;
        upk2(qd, a2, b2);
        a2 = fminf(a2, 88.0f);
        b2 = fminf(b2, 88.0f);
        upk2(q0, c2, d2);
        uint64_t g = pk2(ex2a(c2), ex2a(d2));
        uint64_t d = pk2(ex2a(a2), ex2a(b2));
        uint64_t R = u4.y;

#pragma unroll
        for (int p = 0; p < 8; p++) {
            S2[p] = fma2(g, u2.y, S2[p]);
            uint64_t gg = mul2(g, g);
            S1[p] = fma2(gg, u3.x, S1[p]);
            if (p < 7) {
                g = mul2(g, d);
                d = mul2(d, R);
            }
        }
    }
    // ---- thin pairs: exact ex2 per pixel ----
    for (; kp < 128; kp++) {
        ulonglong2 u0 = sp[kp * 8 + 0];
        ulonglong2 u1 = sp[kp * 8 + 1];
        ulonglong2 u2 = sp[kp * 8 + 2];
        ulonglong2 u3 = sp[kp * 8 + 3];

        uint64_t dy = add2(Y, u2.x);
        uint64_t wv = mul2(mul2(u1.y, dy), dy);
        uint64_t v  = fma2(u0.x, X0, u1.x);
        v = fma2(u0.y, dy, v);
        uint64_t dl = mul2(u3.y, pk2(-0.5f, -0.5f));  // Delta = -DC/2

#pragma unroll
        for (int p = 0; p < 8; p++) {
            uint64_t nv = v ^ SGN;
            uint64_t q  = fma2(v, nv, wv);
            float l, h;
            upk2(q, l, h);
            uint64_t g = pk2(ex2a(l), ex2a(h));
            S2[p] = fma2(g, u2.y, S2[p]);
            uint64_t gg = mul2(g, g);
            S1[p] = fma2(gg, u3.x, S1[p]);
            v = add2(v, dl);
        }
    }

    int p0 = i * 128 + jb;
    float2* dst = g_partial + (size_t)(s * 16 + sub) * 16384;
#pragma unroll
    for (int p = 0; p < 8; p++) {
        float s1l, s1h, s2l, s2h;
        upk2(S1[p], s1l, s1h);
        upk2(S2[p], s2l, s2h);
        dst[p0 + p] = make_float2(s1l + s1h, s2l + s2h);
    }
}

// ---------------------------------------------------------------------------
// Kernel 3: fold subchunks (4 per reference chunk), then transmittance
// recurrence over the 4 chunks (== reference scan).
// ---------------------------------------------------------------------------
__global__ void __launch_bounds__(256) k_fold(float* __restrict__ out) {
    int g = blockIdx.x * 256 + threadIdx.x;   // 65536
    int s = g >> 14;
    int p = g & 16383;
    const float2* base = g_partial + (size_t)s * 16 * 16384 + p;

    float img = 0.0f, T = 1.0f;
#pragma unroll
    for (int c = 0; c < 4; c++) {
        float S1 = 0.0f, S2 = 0.0f;
#pragma unroll
        for (int u = 0; u < 4; u++) {
            float2 v = base[(size_t)(c * 4 + u) * 16384];
            S1 += v.x;
            S2 += v.y;
        }
        img = fmaf(T, S1, img);
        T   = T * (1.0f - S2);
    }
    out[g] = img;   // BACKGROUND == 0
}

// ---------------------------------------------------------------------------
extern "C" void kernel_launch(void* const* d_in, const int* in_sizes, int n_in,
                              void* d_out, int out_size) {
    const float* means  = (const float*)d_in[0];
    const float* scales = (const float*)d_in[1];
    const float* rots   = (const float*)d_in[2];
    const float* opac   = (const float*)d_in[3];
    const float* feat   = (const float*)d_in[4];
    float* out = (float*)d_out;

    k_precompute<<<64, 256>>>(means, scales, rots, opac, feat);
    k_render_part<<<1024, 128>>>();
    k_fold<<<256, 256>>>(out);
}